// round 2
// baseline (speedup 1.0000x reference)
#include <cuda_runtime.h>
#include <cuda_bf16.h>
#include <math.h>

#define H 256
#define SENC 1024
#define NSTEP 256
#define VOCAB 47
#define GPL 32      // CTAs per layer in recurrence kernel
#define UPC 8       // LSTM units per CTA

// ---------------- device scratch (no allocations allowed) ----------------
__device__ float g_xw1[NSTEP * 1024];          // x@W_ih1^T + b_ih1 + b_hh1
__device__ float g_VOutB[H * SENC];            // att_V@outEnc^T + att_b
__device__ float g_H[3][(NSTEP + 1) * H];      // h states per layer (idx 0 = init)
__device__ unsigned g_flag[3 * (NSTEP + 1)];   // per (layer,t) arrival counters

__device__ __forceinline__ float sig_acc(float x) { return 1.0f / (1.0f + expf(-x)); }

__device__ __forceinline__ float tanh_poly(float x) {
    float t = x * x;
    float p = fmaf(t, 0.0218694885f, -0.0539682540f);
    p = fmaf(t, p, 0.1333333333f);
    p = fmaf(t, p, -0.3333333333f);
    float y = fmaf(x * t, p, x);
    if (fabsf(x) > 0.5f) y = tanhf(x);
    return y;
}

// =====================================================================
// Kernel 1: prep — flags/state init, xw1 GEMM, VOutB GEMM
// blocks 0..255: xw1 tiles; 256..511: VOutB tiles; 512: misc
// =====================================================================
__global__ void __launch_bounds__(256) prep_kernel(
    const int* __restrict__ Y, const float* __restrict__ h0,
    const float* __restrict__ emb, const float* __restrict__ W_ih1,
    const float* __restrict__ b_ih1, const float* __restrict__ b_hh1,
    const float* __restrict__ att_V, const float* __restrict__ att_b,
    const float* __restrict__ outEnc)
{
    int bid = blockIdx.x, tid = threadIdx.x;
    if (bid == 512) {
        for (int i = tid; i < 3 * (NSTEP + 1); i += 256) g_flag[i] = 0u;
        if (tid < H) {
            g_H[0][tid] = h0[0 * H + tid];
            g_H[1][tid] = h0[1 * H + tid];
            g_H[2][tid] = h0[2 * H + tid];
        }
        return;
    }
    __shared__ float As[32][33];
    __shared__ float Bs[32][33];
    int mode = bid >> 8;       // 0 -> xw1, 1 -> VOutB
    int tb = bid & 255;
    int m0 = (tb & 7) * 32;    // M = 256
    int n0 = (tb >> 3) * 32;   // N = 1024
    const float* Bsrc = mode ? outEnc : W_ih1;

    int tm = tid & 31;
    int tn = tid >> 5;         // 0..7, 4 n's each
    int ar = tid >> 3, ak = (tid & 7) << 2;

    float acc0 = 0.f, acc1 = 0.f, acc2 = 0.f, acc3 = 0.f;
    for (int k0 = 0; k0 < H; k0 += 32) {
        const float* arow = mode ? (att_V + (m0 + ar) * H) : (emb + Y[m0 + ar] * H);
        float4 a4 = *(const float4*)(arow + k0 + ak);
        As[ar][ak] = a4.x; As[ar][ak + 1] = a4.y; As[ar][ak + 2] = a4.z; As[ar][ak + 3] = a4.w;
        float4 b4 = *(const float4*)(Bsrc + (n0 + ar) * H + k0 + ak);
        Bs[ar][ak] = b4.x; Bs[ar][ak + 1] = b4.y; Bs[ar][ak + 2] = b4.z; Bs[ar][ak + 3] = b4.w;
        __syncthreads();
#pragma unroll
        for (int kk = 0; kk < 32; kk++) {
            float a = As[tm][kk];
            acc0 += a * Bs[tn * 4 + 0][kk];
            acc1 += a * Bs[tn * 4 + 1][kk];
            acc2 += a * Bs[tn * 4 + 2][kk];
            acc3 += a * Bs[tn * 4 + 3][kk];
        }
        __syncthreads();
    }
    int m = m0 + tm;
    float* Cd = mode ? g_VOutB : g_xw1;
    float accs[4] = {acc0, acc1, acc2, acc3};
#pragma unroll
    for (int jj = 0; jj < 4; jj++) {
        int n = n0 + tn * 4 + jj;
        float b = mode ? att_b[m] : (b_ih1[n] + b_hh1[n]);
        Cd[m * 1024 + n] = accs[jj] + b;
    }
}

// =====================================================================
// Kernel 2: persistent layer-pipelined LSTM recurrence.
// =====================================================================
__global__ void __launch_bounds__(256) rnn_kernel(
    const float* __restrict__ c0,
    const float* __restrict__ Wih2, const float* __restrict__ Whh2,
    const float* __restrict__ bih2, const float* __restrict__ bhh2,
    const float* __restrict__ Wih3, const float* __restrict__ Whh3,
    const float* __restrict__ bih3, const float* __restrict__ bhh3,
    const float* __restrict__ Whh1)
{
    extern __shared__ float sm[];
    int tid = threadIdx.x;
    int l = blockIdx.x >> 5;     // layer 0..2
    int p = blockIdx.x & 31;     // part 0..31
    const int RL = (l == 0) ? H : 2 * H;

    float* sW    = sm;                 // up to 32*512
    float* sIn   = sm + 32 * 2 * H;    // 512
    float* sGate = sIn + 2 * H;        // 32
    float* sBias = sGate + 32;         // 32
    float* sC    = sBias + 32;         // 8

    const float* Wih = (l == 1) ? Wih2 : Wih3;
    const float* Whh = (l == 0) ? Whh1 : ((l == 1) ? Whh2 : Whh3);
    const float* bih = (l == 1) ? bih2 : bih3;
    const float* bhh = (l == 1) ? bhh2 : bhh3;

    // preload weights: row rr = gate*8 + unit_local, layout [Wih | Whh]
    int nf4 = 32 * RL / 4;
    for (int idx = tid; idx < nf4; idx += 256) {
        int row = idx / (RL / 4), c4 = idx % (RL / 4);
        int gate = row >> 3, ul = row & 7;
        int grow = gate * H + p * UPC + ul;
        const float* src;
        if (l == 0) src = Whh + grow * H + c4 * 4;
        else        src = (c4 < 64) ? (Wih + grow * H + c4 * 4)
                                    : (Whh + grow * H + (c4 - 64) * 4);
        *(float4*)(sW + row * RL + c4 * 4) = *(const float4*)src;
    }
    if (l > 0 && tid < 32) {
        int gate = tid >> 3, ul = tid & 7;
        int grow = gate * H + p * UPC + ul;
        sBias[tid] = bih[grow] + bhh[grow];
    }
    if (tid < UPC) sC[tid] = c0[l * H + p * UPC + tid];
    __syncthreads();

    int warp = tid >> 5, lane = tid & 31;
    const float4* xi  = (const float4*)sIn;
    const float4* w0  = (const float4*)(sW + (warp)      * RL);
    const float4* w1p = (const float4*)(sW + (warp + 8)  * RL);
    const float4* w2p = (const float4*)(sW + (warp + 16) * RL);
    const float4* w3p = (const float4*)(sW + (warp + 24) * RL);

    volatile unsigned* flagL = (volatile unsigned*)(g_flag + l * (NSTEP + 1));
    volatile unsigned* flagD = (l > 0) ? (volatile unsigned*)(g_flag + (l - 1) * (NSTEP + 1))
                                       : (volatile unsigned*)(g_flag + l * (NSTEP + 1));

    for (int t = 1; t <= NSTEP; t++) {
        float a0 = 0.f, a1 = 0.f, a2 = 0.f, a3 = 0.f;
        if (l > 0) {
            if (tid == 0) { while (flagD[t] < GPL) {} __threadfence(); }
            __syncthreads();
            sIn[tid] = __ldcg(&g_H[l - 1][t * H + tid]);
            __syncthreads();
#pragma unroll
            for (int m = 0; m < 2; m++) {
                int k4 = lane + 32 * m;
                float4 x = xi[k4]; float4 w;
                w = w0[k4];  a0 += w.x * x.x + w.y * x.y + w.z * x.z + w.w * x.w;
                w = w1p[k4]; a1 += w.x * x.x + w.y * x.y + w.z * x.z + w.w * x.w;
                w = w2p[k4]; a2 += w.x * x.x + w.y * x.y + w.z * x.z + w.w * x.w;
                w = w3p[k4]; a3 += w.x * x.x + w.y * x.y + w.z * x.z + w.w * x.w;
            }
            if (tid == 0 && t > 1) { while (flagL[t - 1] < GPL) {} __threadfence(); }
            __syncthreads();
            sIn[H + tid] = __ldcg(&g_H[l][(t - 1) * H + tid]);
            __syncthreads();
#pragma unroll
            for (int m = 2; m < 4; m++) {
                int k4 = lane + 32 * m;
                float4 x = xi[k4]; float4 w;
                w = w0[k4];  a0 += w.x * x.x + w.y * x.y + w.z * x.z + w.w * x.w;
                w = w1p[k4]; a1 += w.x * x.x + w.y * x.y + w.z * x.z + w.w * x.w;
                w = w2p[k4]; a2 += w.x * x.x + w.y * x.y + w.z * x.z + w.w * x.w;
                w = w3p[k4]; a3 += w.x * x.x + w.y * x.y + w.z * x.z + w.w * x.w;
            }
        } else {
            if (tid == 0 && t > 1) { while (flagL[t - 1] < GPL) {} __threadfence(); }
            __syncthreads();
            sIn[tid] = __ldcg(&g_H[0][(t - 1) * H + tid]);
            if (tid < 32) {
                int gate = tid >> 3, ul = tid & 7;
                sBias[tid] = __ldcg(&g_xw1[(t - 1) * 1024 + gate * H + p * UPC + ul]);
            }
            __syncthreads();
#pragma unroll
            for (int m = 0; m < 2; m++) {
                int k4 = lane + 32 * m;
                float4 x = xi[k4]; float4 w;
                w = w0[k4];  a0 += w.x * x.x + w.y * x.y + w.z * x.z + w.w * x.w;
                w = w1p[k4]; a1 += w.x * x.x + w.y * x.y + w.z * x.z + w.w * x.w;
                w = w2p[k4]; a2 += w.x * x.x + w.y * x.y + w.z * x.z + w.w * x.w;
                w = w3p[k4]; a3 += w.x * x.x + w.y * x.y + w.z * x.z + w.w * x.w;
            }
        }
#pragma unroll
        for (int off = 1; off < 32; off <<= 1) {
            a0 += __shfl_xor_sync(0xffffffffu, a0, off);
            a1 += __shfl_xor_sync(0xffffffffu, a1, off);
            a2 += __shfl_xor_sync(0xffffffffu, a2, off);
            a3 += __shfl_xor_sync(0xffffffffu, a3, off);
        }
        if (lane == 0) {
            sGate[0 * 8 + warp] = a0;
            sGate[1 * 8 + warp] = a1;
            sGate[2 * 8 + warp] = a2;
            sGate[3 * 8 + warp] = a3;
        }
        __syncthreads();
        if (tid < UPC) {
            float gi = sGate[tid]      + sBias[tid];
            float gf = sGate[8 + tid]  + sBias[8 + tid];
            float gg = sGate[16 + tid] + sBias[16 + tid];
            float go = sGate[24 + tid] + sBias[24 + tid];
            float c = sig_acc(gf) * sC[tid] + sig_acc(gi) * tanhf(gg);
            float hh = sig_acc(go) * tanhf(c);
            sC[tid] = c;
            __stcg(&g_H[l][t * H + p * UPC + tid], hh);
        }
        __syncthreads();
        if (tid == 0) { __threadfence(); atomicAdd((unsigned*)&flagL[t], 1u); }
    }
}

// =====================================================================
// Kernel 3: attention + MLP head, one block per timestep.
// =====================================================================
__global__ void __launch_bounds__(256) attn_kernel(
    const float* __restrict__ outEnc, const float* __restrict__ attW,
    const float* __restrict__ attVec,
    const float* __restrict__ w1, const float* __restrict__ b1,
    const float* __restrict__ w2, const float* __restrict__ b2,
    const float* __restrict__ w3, const float* __restrict__ b3,
    float* __restrict__ outp)
{
    __shared__ float h2s[H];
    __shared__ float wss[H];
    __shared__ float avs[H];
    __shared__ float alp[SENC];
    __shared__ float red[20];
    __shared__ float vbuf[2 * H];
    __shared__ float v1s[H];
    __shared__ float v2s[H];

    int tid = threadIdx.x;
    int t = blockIdx.x;
    int lane = tid & 31, warp = tid >> 5;

    avs[tid] = attVec[tid];
    h2s[tid] = __ldcg(&g_H[2][(t + 1) * H + tid]);
    __syncthreads();

    // WS[h] = att_W[h,:] . h2
    {
        float s = 0.f;
        const float4* wr = (const float4*)(attW + tid * H);
        const float4* x = (const float4*)h2s;
#pragma unroll 8
        for (int k = 0; k < 64; k++) {
            float4 w = wr[k], a = x[k];
            s += w.x * a.x + w.y * a.y + w.z * a.z + w.w * a.w;
        }
        wss[tid] = s;
    }
    __syncthreads();

    // e[s] = sum_h av[h] * tanh(WS[h] + VOutB[h][s]);  s = 4*tid + j
    float e0 = 0.f, e1 = 0.f, e2 = 0.f, e3 = 0.f;
    const float4* vb = (const float4*)g_VOutB;
#pragma unroll 4
    for (int h = 0; h < H; h++) {
        float a = avs[h], w = wss[h];
        float4 v4 = vb[h * (SENC / 4) + tid];
        e0 = fmaf(a, tanh_poly(w + v4.x), e0);
        e1 = fmaf(a, tanh_poly(w + v4.y), e1);
        e2 = fmaf(a, tanh_poly(w + v4.z), e2);
        e3 = fmaf(a, tanh_poly(w + v4.w), e3);
    }

    // softmax over 1024
    float mx = fmaxf(fmaxf(e0, e1), fmaxf(e2, e3));
#pragma unroll
    for (int off = 16; off > 0; off >>= 1) mx = fmaxf(mx, __shfl_xor_sync(0xffffffffu, mx, off));
    if (lane == 0) red[warp] = mx;
    __syncthreads();
    if (tid == 0) {
        float m = red[0];
#pragma unroll
        for (int i = 1; i < 8; i++) m = fmaxf(m, red[i]);
        red[16] = m;
    }
    __syncthreads();
    mx = red[16];
    float x0 = __expf(e0 - mx), x1 = __expf(e1 - mx), x2 = __expf(e2 - mx), x3 = __expf(e3 - mx);
    float sm = x0 + x1 + x2 + x3;
#pragma unroll
    for (int off = 16; off > 0; off >>= 1) sm += __shfl_xor_sync(0xffffffffu, sm, off);
    if (lane == 0) red[warp + 8] = sm;
    __syncthreads();
    if (tid == 0) {
        float s = 0.f;
#pragma unroll
        for (int i = 0; i < 8; i++) s += red[8 + i];
        red[17] = 1.0f / s;
    }
    __syncthreads();
    float inv = red[17];
    alp[4 * tid + 0] = x0 * inv;
    alp[4 * tid + 1] = x1 * inv;
    alp[4 * tid + 2] = x2 * inv;
    alp[4 * tid + 3] = x3 * inv;
    __syncthreads();

    // context[tid] = sum_s alpha[s] * outEnc[s][tid]
    float ctx = 0.f;
#pragma unroll 4
    for (int s = 0; s < SENC; s += 4) {
        ctx = fmaf(alp[s + 0], __ldg(&outEnc[(s + 0) * H + tid]), ctx);
        ctx = fmaf(alp[s + 1], __ldg(&outEnc[(s + 1) * H + tid]), ctx);
        ctx = fmaf(alp[s + 2], __ldg(&outEnc[(s + 2) * H + tid]), ctx);
        ctx = fmaf(alp[s + 3], __ldg(&outEnc[(s + 3) * H + tid]), ctx);
    }
    vbuf[tid] = h2s[tid];
    vbuf[H + tid] = ctx;
    __syncthreads();

    // v1 = relu(v @ w1^T + b1)  -- w1 rows of length 512
    {
        float s = b1[tid];
        const float4* r = (const float4*)(w1 + tid * (2 * H));
        const float4* x = (const float4*)vbuf;
#pragma unroll 8
        for (int k = 0; k < 128; k++) {
            float4 w = r[k], a = x[k];
            s += w.x * a.x + w.y * a.y + w.z * a.z + w.w * a.w;
        }
        v1s[tid] = fmaxf(s, 0.f);
    }
    __syncthreads();
    // v2 = relu(v1 @ w2^T + b2)
    {
        float s = b2[tid];
        const float4* r = (const float4*)(w2 + tid * H);
        const float4* x = (const float4*)v1s;
#pragma unroll 8
        for (int k = 0; k < 64; k++) {
            float4 w = r[k], a = x[k];
            s += w.x * a.x + w.y * a.y + w.z * a.z + w.w * a.w;
        }
        v2s[tid] = fmaxf(s, 0.f);
    }
    __syncthreads();
    // out = v2 @ w3^T + b3
    if (tid < VOCAB) {
        float s = b3[tid];
        const float4* r = (const float4*)(w3 + tid * H);
        const float4* x = (const float4*)v2s;
#pragma unroll 8
        for (int k = 0; k < 64; k++) {
            float4 w = r[k], a = x[k];
            s += w.x * a.x + w.y * a.y + w.z * a.z + w.w * a.w;
        }
        outp[t * VOCAB + tid] = s;
    }
}

extern "C" void kernel_launch(void* const* d_in, const int* in_sizes, int n_in,
                              void* d_out, int out_size) {
    const int*   Y      = (const int*)d_in[0];
    const float* h0     = (const float*)d_in[1];
    const float* c0     = (const float*)d_in[2];
    const float* outEnc = (const float*)d_in[3];
    const float* emb    = (const float*)d_in[4];
    const float* W_ih1  = (const float*)d_in[5];
    const float* W_hh1  = (const float*)d_in[6];
    const float* b_ih1  = (const float*)d_in[7];
    const float* b_hh1  = (const float*)d_in[8];
    const float* W_ih2  = (const float*)d_in[9];
    const float* W_hh2  = (const float*)d_in[10];
    const float* b_ih2  = (const float*)d_in[11];
    const float* b_hh2  = (const float*)d_in[12];
    const float* W_ih3  = (const float*)d_in[13];
    const float* W_hh3  = (const float*)d_in[14];
    const float* b_ih3  = (const float*)d_in[15];
    const float* b_hh3  = (const float*)d_in[16];
    const float* attVec = (const float*)d_in[17];
    const float* attW   = (const float*)d_in[18];
    const float* attV   = (const float*)d_in[19];
    const float* attB   = (const float*)d_in[20];
    const float* w1     = (const float*)d_in[21];
    const float* b1     = (const float*)d_in[22];
    const float* w2     = (const float*)d_in[23];
    const float* b2     = (const float*)d_in[24];
    const float* w3     = (const float*)d_in[25];
    const float* b3     = (const float*)d_in[26];
    float* outp = (float*)d_out;

    size_t rnn_smem = (size_t)(32 * 2 * H + 2 * H + 32 + 32 + 8) * sizeof(float);
    cudaFuncSetAttribute(rnn_kernel, cudaFuncAttributeMaxDynamicSharedMemorySize, (int)rnn_smem);

    prep_kernel<<<513, 256>>>(Y, h0, emb, W_ih1, b_ih1, b_hh1, attV, attB, outEnc);
    rnn_kernel<<<96, 256, rnn_smem>>>(c0, W_ih2, W_hh2, b_ih2, b_hh2,
                                      W_ih3, W_hh3, b_ih3, b_hh3, W_hh1);
    attn_kernel<<<NSTEP, 256>>>(outEnc, attW, attVec, w1, b1, w2, b2, w3, b3, outp);
}

// round 5
// speedup vs baseline: 1.4065x; 1.4065x over previous
#include <cuda_runtime.h>
#include <cuda_bf16.h>
#include <math.h>

#define H 256
#define SENC 1024
#define NSTEP 256
#define VOCAB 47
#define UPC 8
#define LSTRIDE ((NSTEP + 1) * H)
#define RNN_BLOCKS 96
#define ATTN_BLOCKS 128

// ---------------- device scratch ----------------
__device__ float g_xw1[NSTEP * 1024];              // emb[Y[t]]@W_ih1^T + b_ih1 + b_hh1
__device__ float g_VOutB[H * SENC];                // att_V@outEnc^T + att_b
__device__ unsigned long long g_Ht64[3 * LSTRIDE]; // packed {tag<<32 | float bits}

// accurate math for the recurrence path (R2-proven)
__device__ __forceinline__ float sig_acc(float x) { return 1.0f / (1.0f + expf(-x)); }

// accurate-enough tanh for attention path (R2-proven)
__device__ __forceinline__ float tanh_poly(float x) {
    float t = x * x;
    float p = fmaf(t, 0.0218694885f, -0.0539682540f);
    p = fmaf(t, p, 0.1333333333f);
    p = fmaf(t, p, -0.3333333333f);
    float y = fmaf(x * t, p, x);
    if (fabsf(x) > 0.5f) y = tanhf(x);
    return y;
}

// 64-bit scalar acquire/release tag word: guaranteed single-copy atomic.
__device__ __forceinline__ float poll_tag(const unsigned long long* a, unsigned tag) {
    unsigned long long w;
    do {
        asm volatile("ld.acquire.gpu.global.b64 %0,[%1];" : "=l"(w) : "l"(a) : "memory");
    } while ((unsigned)(w >> 32) != tag);
    return __uint_as_float((unsigned)w);
}
__device__ __forceinline__ void store_tag(unsigned long long* a, float v, unsigned tag) {
    unsigned long long w = ((unsigned long long)tag << 32) |
                           (unsigned long long)__float_as_uint(v);
    asm volatile("st.release.gpu.global.b64 [%0],%1;" :: "l"(a), "l"(w) : "memory");
}

// =====================================================================
// Kernel 1: prep — tag clear + init, xw1 GEMM, VOutB GEMM
// blocks 0..255: xw1 tiles; 256..511: VOutB tiles; 512..519: tags/init
// =====================================================================
__global__ void __launch_bounds__(256) prep_kernel(
    const int* __restrict__ Y, const float* __restrict__ h0,
    const float* __restrict__ emb, const float* __restrict__ W_ih1,
    const float* __restrict__ b_ih1, const float* __restrict__ b_hh1,
    const float* __restrict__ att_V, const float* __restrict__ att_b,
    const float* __restrict__ outEnc)
{
    int bid = blockIdx.x, tid = threadIdx.x;
    if (bid >= 512) {
        int base = (bid - 512) * 256 + tid;
        for (int i = base; i < 3 * NSTEP * H; i += 8 * 256) {
            int l = i / (NSTEP * H);
            int rem = i - l * (NSTEP * H);
            int t = rem / H + 1;
            int u = rem % H;
            g_Ht64[l * LSTRIDE + t * H + u] = 0xFFFFFFFF00000000ULL;
        }
        if (bid == 519) {  // t=0 slots, tag 0 (disjoint from clears)
            store_tag(&g_Ht64[0 * LSTRIDE + tid], h0[0 * H + tid], 0u);
            store_tag(&g_Ht64[1 * LSTRIDE + tid], h0[1 * H + tid], 0u);
            store_tag(&g_Ht64[2 * LSTRIDE + tid], h0[2 * H + tid], 0u);
        }
        return;
    }
    __shared__ float As[32][33];
    __shared__ float Bs[32][33];
    int mode = bid >> 8;       // 0 -> xw1, 1 -> VOutB
    int tb = bid & 255;
    int m0 = (tb & 7) * 32;
    int n0 = (tb >> 3) * 32;
    const float* Bsrc = mode ? outEnc : W_ih1;

    int tm = tid & 31;
    int tn = tid >> 5;
    int ar = tid >> 3, ak = (tid & 7) << 2;

    float acc0 = 0.f, acc1 = 0.f, acc2 = 0.f, acc3 = 0.f;
    for (int k0 = 0; k0 < H; k0 += 32) {
        const float* arow = mode ? (att_V + (m0 + ar) * H) : (emb + Y[m0 + ar] * H);
        float4 a4 = *(const float4*)(arow + k0 + ak);
        As[ar][ak] = a4.x; As[ar][ak + 1] = a4.y; As[ar][ak + 2] = a4.z; As[ar][ak + 3] = a4.w;
        float4 b4 = *(const float4*)(Bsrc + (n0 + ar) * H + k0 + ak);
        Bs[ar][ak] = b4.x; Bs[ar][ak + 1] = b4.y; Bs[ar][ak + 2] = b4.z; Bs[ar][ak + 3] = b4.w;
        __syncthreads();
#pragma unroll
        for (int kk = 0; kk < 32; kk++) {
            float a = As[tm][kk];
            acc0 += a * Bs[tn * 4 + 0][kk];
            acc1 += a * Bs[tn * 4 + 1][kk];
            acc2 += a * Bs[tn * 4 + 2][kk];
            acc3 += a * Bs[tn * 4 + 3][kk];
        }
        __syncthreads();
    }
    int m = m0 + tm;
    float* Cd = mode ? g_VOutB : g_xw1;
    float accs[4] = {acc0, acc1, acc2, acc3};
#pragma unroll
    for (int jj = 0; jj < 4; jj++) {
        int n = n0 + tn * 4 + jj;
        float b = mode ? att_b[m] : (b_ih1[n] + b_hh1[n]);
        Cd[m * 1024 + n] = accs[jj] + b;
    }
}

// =====================================================================
// Kernel 2 (fused): blocks 0..95 = persistent LSTM recurrence,
//                   blocks 96..223 = attention+MLP (2 steps each, polling h2)
// =====================================================================
__global__ void __launch_bounds__(256) fused_kernel(
    const float* __restrict__ h0, const float* __restrict__ c0,
    const float* __restrict__ Wih2, const float* __restrict__ Whh2,
    const float* __restrict__ bih2, const float* __restrict__ bhh2,
    const float* __restrict__ Wih3, const float* __restrict__ Whh3,
    const float* __restrict__ bih3, const float* __restrict__ bhh3,
    const float* __restrict__ Whh1,
    const float* __restrict__ outEnc, const float* __restrict__ attW,
    const float* __restrict__ attVec,
    const float* __restrict__ w1, const float* __restrict__ b1,
    const float* __restrict__ w2, const float* __restrict__ b2,
    const float* __restrict__ w3, const float* __restrict__ b3,
    float* __restrict__ outp)
{
    // ---- rnn shared ----
    __shared__ float sIn[2 * H];
    __shared__ float sGate[32];
    __shared__ float sBias[2][32];
    __shared__ float sAct[32];
    // ---- attn shared ----
    __shared__ float h2s[2][H];
    __shared__ float wss[2][H];
    __shared__ float avs[H];
    __shared__ float alp[2][SENC];
    __shared__ float red[40];
    __shared__ float vbuf[2][2 * H];
    __shared__ float v1s[2][H];
    __shared__ float v2s[2][H];

    int tid = threadIdx.x, lane = tid & 31, warp = tid >> 5;

    if (blockIdx.x < RNN_BLOCKS) {
        // ============================ RNN ============================
        int l = blockIdx.x >> 5;
        int p = blockIdx.x & 31;

        const float* Wih = (l == 1) ? Wih2 : ((l == 2) ? Wih3 : (const float*)0);
        const float* Whh = (l == 0) ? Whh1 : ((l == 1) ? Whh2 : Whh3);
        const float* bih = (l == 1) ? bih2 : bih3;
        const float* bhh = (l == 1) ? bhh2 : bhh3;

        // weights into registers: warp handles unit p*8+warp, r = gate
        float4 W[4][4];
#pragma unroll
        for (int r = 0; r < 4; r++) {
            int grow = r * H + p * UPC + warp;
            if (Wih) {
                W[r][0] = *(const float4*)(Wih + grow * H + 4 * lane);
                W[r][1] = *(const float4*)(Wih + grow * H + 4 * (lane + 32));
            } else {
                W[r][0] = make_float4(0.f, 0.f, 0.f, 0.f);
                W[r][1] = make_float4(0.f, 0.f, 0.f, 0.f);
            }
            W[r][2] = *(const float4*)(Whh + grow * H + 4 * lane);
            W[r][3] = *(const float4*)(Whh + grow * H + 4 * (lane + 32));
        }
        if (l > 0 && tid < 32) {
            int g = tid >> 3, u = tid & 7;
            int grow = g * H + p * UPC + u;
            float b = bih[grow] + bhh[grow];
            sBias[0][tid] = b; sBias[1][tid] = b;
        }
        if (l == 0) sIn[tid] = 0.f;   // x-part folded into g_xw1 bias

        float creg = 0.f, hreg = 0.f;
        if (tid < UPC) {
            creg = c0[l * H + p * UPC + tid];
            hreg = h0[l * H + p * UPC + tid];
        }
        __syncthreads();

        unsigned long long* ownB = g_Ht64 + l * LSTRIDE;
        unsigned long long* depB = g_Ht64 + (l - 1) * LSTRIDE;
        bool ownSlot = (tid >= p * UPC) && (tid < p * UPC + UPC);

        for (unsigned t = 1; t <= NSTEP; t++) {
            if (tid < UPC) sIn[H + p * UPC + tid] = hreg;
            if (!ownSlot) sIn[H + tid] = poll_tag(ownB + (t - 1) * H + tid, t - 1);
            if (l > 0) {
                sIn[tid] = poll_tag(depB + t * H + tid, t);
            } else if (tid < 32) {
                sBias[t & 1][tid] =
                    __ldcg(&g_xw1[(t - 1) * 1024 + (tid >> 3) * H + p * UPC + (tid & 7)]);
            }
            __syncthreads();

            float a0 = 0.f, a1 = 0.f, a2 = 0.f, a3 = 0.f;
#pragma unroll
            for (int m = 0; m < 4; m++) {
                float4 x = *(const float4*)(sIn + 4 * (lane + 32 * m));
                a0 = fmaf(W[0][m].x, x.x, a0); a0 = fmaf(W[0][m].y, x.y, a0);
                a0 = fmaf(W[0][m].z, x.z, a0); a0 = fmaf(W[0][m].w, x.w, a0);
                a1 = fmaf(W[1][m].x, x.x, a1); a1 = fmaf(W[1][m].y, x.y, a1);
                a1 = fmaf(W[1][m].z, x.z, a1); a1 = fmaf(W[1][m].w, x.w, a1);
                a2 = fmaf(W[2][m].x, x.x, a2); a2 = fmaf(W[2][m].y, x.y, a2);
                a2 = fmaf(W[2][m].z, x.z, a2); a2 = fmaf(W[2][m].w, x.w, a2);
                a3 = fmaf(W[3][m].x, x.x, a3); a3 = fmaf(W[3][m].y, x.y, a3);
                a3 = fmaf(W[3][m].z, x.z, a3); a3 = fmaf(W[3][m].w, x.w, a3);
            }
#pragma unroll
            for (int off = 16; off > 0; off >>= 1) {
                a0 += __shfl_xor_sync(0xffffffffu, a0, off);
                a1 += __shfl_xor_sync(0xffffffffu, a1, off);
                a2 += __shfl_xor_sync(0xffffffffu, a2, off);
                a3 += __shfl_xor_sync(0xffffffffu, a3, off);
            }
            if (lane == 0) {
                sGate[0 + warp]  = a0;
                sGate[8 + warp]  = a1;
                sGate[16 + warp] = a2;
                sGate[24 + warp] = a3;
            }
            __syncthreads();
            if (tid < 32) {   // entire warp 0: parallel activations
                float raw = sGate[tid] + sBias[t & 1][tid];
                float act = (tid >= 16 && tid < 24) ? tanhf(raw) : sig_acc(raw);
                sAct[tid] = act;
                __syncwarp();
                if (tid < UPC) {
                    float c = sAct[8 + tid] * creg + sAct[tid] * sAct[16 + tid];
                    float h = sAct[24 + tid] * tanhf(c);
                    creg = c; hreg = h;
                    store_tag(ownB + t * H + p * UPC + tid, h, t);
                }
            }
            // sGate/sAct rewritten only after the next iteration's barriers;
            // sBias double-buffered; sIn not read in the cell phase.
        }
        return;
    }

    // ============================ ATTENTION + MLP ============================
    int t0 = (blockIdx.x - RNN_BLOCKS) * 2;

    avs[tid] = attVec[tid];
    h2s[0][tid] = poll_tag(&g_Ht64[2 * LSTRIDE + (t0 + 1) * H + tid], (unsigned)(t0 + 1));
    h2s[1][tid] = poll_tag(&g_Ht64[2 * LSTRIDE + (t0 + 2) * H + tid], (unsigned)(t0 + 2));
    __syncthreads();

    // WS[s][h] = att_W[h,:] . h2[s]
    {
        float s0 = 0.f, s1 = 0.f;
        const float4* wr = (const float4*)(attW + tid * H);
        const float4* x0 = (const float4*)h2s[0];
        const float4* x1 = (const float4*)h2s[1];
#pragma unroll 8
        for (int k = 0; k < 64; k++) {
            float4 w = wr[k], a = x0[k], b = x1[k];
            s0 += w.x * a.x + w.y * a.y + w.z * a.z + w.w * a.w;
            s1 += w.x * b.x + w.y * b.y + w.z * b.z + w.w * b.w;
        }
        wss[0][tid] = s0; wss[1][tid] = s1;
    }
    __syncthreads();

    // e[s] = sum_h av[h] * tanh(WS[h] + VOutB[h][s]) for both steps
    float e00 = 0.f, e01 = 0.f, e02 = 0.f, e03 = 0.f;
    float e10 = 0.f, e11 = 0.f, e12 = 0.f, e13 = 0.f;
    const float4* vb = (const float4*)g_VOutB;
#pragma unroll 4
    for (int h = 0; h < H; h++) {
        float a = avs[h], w0v = wss[0][h], w1v = wss[1][h];
        float4 v4 = vb[h * (SENC / 4) + tid];
        e00 = fmaf(a, tanh_poly(w0v + v4.x), e00);
        e01 = fmaf(a, tanh_poly(w0v + v4.y), e01);
        e02 = fmaf(a, tanh_poly(w0v + v4.z), e02);
        e03 = fmaf(a, tanh_poly(w0v + v4.w), e03);
        e10 = fmaf(a, tanh_poly(w1v + v4.x), e10);
        e11 = fmaf(a, tanh_poly(w1v + v4.y), e11);
        e12 = fmaf(a, tanh_poly(w1v + v4.z), e12);
        e13 = fmaf(a, tanh_poly(w1v + v4.w), e13);
    }

    // softmax over 1024, both steps
    float mx0 = fmaxf(fmaxf(e00, e01), fmaxf(e02, e03));
    float mx1 = fmaxf(fmaxf(e10, e11), fmaxf(e12, e13));
#pragma unroll
    for (int off = 16; off > 0; off >>= 1) {
        mx0 = fmaxf(mx0, __shfl_xor_sync(0xffffffffu, mx0, off));
        mx1 = fmaxf(mx1, __shfl_xor_sync(0xffffffffu, mx1, off));
    }
    if (lane == 0) { red[warp] = mx0; red[8 + warp] = mx1; }
    __syncthreads();
    if (tid == 0) {
        float m0 = red[0], m1 = red[8];
#pragma unroll
        for (int i = 1; i < 8; i++) { m0 = fmaxf(m0, red[i]); m1 = fmaxf(m1, red[8 + i]); }
        red[32] = m0; red[33] = m1;
    }
    __syncthreads();
    mx0 = red[32]; mx1 = red[33];
    float x00 = __expf(e00 - mx0), x01 = __expf(e01 - mx0);
    float x02 = __expf(e02 - mx0), x03 = __expf(e03 - mx0);
    float x10 = __expf(e10 - mx1), x11 = __expf(e11 - mx1);
    float x12 = __expf(e12 - mx1), x13 = __expf(e13 - mx1);
    float sm0 = x00 + x01 + x02 + x03;
    float sm1 = x10 + x11 + x12 + x13;
#pragma unroll
    for (int off = 16; off > 0; off >>= 1) {
        sm0 += __shfl_xor_sync(0xffffffffu, sm0, off);
        sm1 += __shfl_xor_sync(0xffffffffu, sm1, off);
    }
    if (lane == 0) { red[16 + warp] = sm0; red[24 + warp] = sm1; }
    __syncthreads();
    if (tid == 0) {
        float s0 = 0.f, s1 = 0.f;
#pragma unroll
        for (int i = 0; i < 8; i++) { s0 += red[16 + i]; s1 += red[24 + i]; }
        red[34] = 1.0f / s0;
        red[35] = 1.0f / s1;
    }
    __syncthreads();
    float inv0 = red[34], inv1 = red[35];
    alp[0][4 * tid + 0] = x00 * inv0; alp[0][4 * tid + 1] = x01 * inv0;
    alp[0][4 * tid + 2] = x02 * inv0; alp[0][4 * tid + 3] = x03 * inv0;
    alp[1][4 * tid + 0] = x10 * inv1; alp[1][4 * tid + 1] = x11 * inv1;
    alp[1][4 * tid + 2] = x12 * inv1; alp[1][4 * tid + 3] = x13 * inv1;
    __syncthreads();

    // context[tid] = sum_s alpha[s] * outEnc[s][tid]
    float c0v = 0.f, c1v = 0.f;
#pragma unroll 4
    for (int s = 0; s < SENC; s++) {
        float v = __ldg(&outEnc[s * H + tid]);
        c0v = fmaf(alp[0][s], v, c0v);
        c1v = fmaf(alp[1][s], v, c1v);
    }
    vbuf[0][tid] = h2s[0][tid]; vbuf[0][H + tid] = c0v;
    vbuf[1][tid] = h2s[1][tid]; vbuf[1][H + tid] = c1v;
    __syncthreads();

    // v1 = relu(v @ w1^T + b1)
    {
        float s0 = b1[tid], s1 = s0;
        const float4* r = (const float4*)(w1 + tid * (2 * H));
        const float4* xa = (const float4*)vbuf[0];
        const float4* xb = (const float4*)vbuf[1];
#pragma unroll 8
        for (int k = 0; k < 128; k++) {
            float4 w = r[k], a = xa[k], b = xb[k];
            s0 += w.x * a.x + w.y * a.y + w.z * a.z + w.w * a.w;
            s1 += w.x * b.x + w.y * b.y + w.z * b.z + w.w * b.w;
        }
        v1s[0][tid] = fmaxf(s0, 0.f);
        v1s[1][tid] = fmaxf(s1, 0.f);
    }
    __syncthreads();
    // v2 = relu(v1 @ w2^T + b2)
    {
        float s0 = b2[tid], s1 = s0;
        const float4* r = (const float4*)(w2 + tid * H);
        const float4* xa = (const float4*)v1s[0];
        const float4* xb = (const float4*)v1s[1];
#pragma unroll 8
        for (int k = 0; k < 64; k++) {
            float4 w = r[k], a = xa[k], b = xb[k];
            s0 += w.x * a.x + w.y * a.y + w.z * a.z + w.w * a.w;
            s1 += w.x * b.x + w.y * b.y + w.z * b.z + w.w * b.w;
        }
        v2s[0][tid] = fmaxf(s0, 0.f);
        v2s[1][tid] = fmaxf(s1, 0.f);
    }
    __syncthreads();
    // out = v2 @ w3^T + b3
    if (tid < VOCAB) {
        float s0 = b3[tid], s1 = s0;
        const float4* r = (const float4*)(w3 + tid * H);
        const float4* xa = (const float4*)v2s[0];
        const float4* xb = (const float4*)v2s[1];
#pragma unroll 8
        for (int k = 0; k < 64; k++) {
            float4 w = r[k], a = xa[k], b = xb[k];
            s0 += w.x * a.x + w.y * a.y + w.z * a.z + w.w * a.w;
            s1 += w.x * b.x + w.y * b.y + w.z * b.z + w.w * b.w;
        }
        outp[(t0 + 0) * VOCAB + tid] = s0;
        outp[(t0 + 1) * VOCAB + tid] = s1;
    }
}

extern "C" void kernel_launch(void* const* d_in, const int* in_sizes, int n_in,
                              void* d_out, int out_size) {
    const int*   Y      = (const int*)d_in[0];
    const float* h0     = (const float*)d_in[1];
    const float* c0     = (const float*)d_in[2];
    const float* outEnc = (const float*)d_in[3];
    const float* emb    = (const float*)d_in[4];
    const float* W_ih1  = (const float*)d_in[5];
    const float* W_hh1  = (const float*)d_in[6];
    const float* b_ih1  = (const float*)d_in[7];
    const float* b_hh1  = (const float*)d_in[8];
    const float* W_ih2  = (const float*)d_in[9];
    const float* W_hh2  = (const float*)d_in[10];
    const float* b_ih2  = (const float*)d_in[11];
    const float* b_hh2  = (const float*)d_in[12];
    const float* W_ih3  = (const float*)d_in[13];
    const float* W_hh3  = (const float*)d_in[14];
    const float* b_ih3  = (const float*)d_in[15];
    const float* b_hh3  = (const float*)d_in[16];
    const float* attVec = (const float*)d_in[17];
    const float* attW   = (const float*)d_in[18];
    const float* attV   = (const float*)d_in[19];
    const float* attB   = (const float*)d_in[20];
    const float* w1     = (const float*)d_in[21];
    const float* b1     = (const float*)d_in[22];
    const float* w2     = (const float*)d_in[23];
    const float* b2     = (const float*)d_in[24];
    const float* w3     = (const float*)d_in[25];
    const float* b3     = (const float*)d_in[26];
    float* outp = (float*)d_out;

    prep_kernel<<<520, 256>>>(Y, h0, emb, W_ih1, b_ih1, b_hh1, attV, attB, outEnc);
    fused_kernel<<<RNN_BLOCKS + ATTN_BLOCKS, 256>>>(
        h0, c0, W_ih2, W_hh2, b_ih2, b_hh2, W_ih3, W_hh3, b_ih3, b_hh3, W_hh1,
        outEnc, attW, attVec, w1, b1, w2, b2, w3, b3, outp);
}

// round 6
// speedup vs baseline: 1.5277x; 1.0862x over previous
#include <cuda_runtime.h>
#include <cuda_bf16.h>
#include <math.h>

#define H 256
#define SENC 1024
#define NSTEP 256
#define VOCAB 47
#define UPC 8
#define LSTRIDE ((NSTEP + 1) * H)
#define RNN_BLOCKS 96
#define ATTN_BLOCKS 128

// ---------------- device scratch ----------------
__device__ float g_xw1[NSTEP * 1024];              // emb[Y[t]]@W_ih1^T + b_ih1 + b_hh1
__device__ float g_VOutB[H * SENC];                // att_V@outEnc^T + att_b
__device__ unsigned long long g_Ht64[3 * LSTRIDE]; // packed {tag<<32 | float bits}

// accurate-enough tanh for attention path (R2/R5-proven)
__device__ __forceinline__ float tanh_poly(float x) {
    float t = x * x;
    float p = fmaf(t, 0.0218694885f, -0.0539682540f);
    p = fmaf(t, p, 0.1333333333f);
    p = fmaf(t, p, -0.3333333333f);
    float y = fmaf(x * t, p, x);
    if (fabsf(x) > 0.5f) y = tanhf(x);
    return y;
}

// ---- 64-bit scalar relaxed tag word: single-copy atomic, value rides with tag ----
__device__ __forceinline__ unsigned long long ld_tag(const unsigned long long* a) {
    unsigned long long w;
    asm volatile("ld.relaxed.gpu.global.b64 %0,[%1];" : "=l"(w) : "l"(a) : "memory");
    return w;
}
__device__ __forceinline__ void store_tag(unsigned long long* a, float v, unsigned tag) {
    unsigned long long w = ((unsigned long long)tag << 32) |
                           (unsigned long long)__float_as_uint(v);
    asm volatile("st.relaxed.gpu.global.b64 [%0],%1;" :: "l"(a), "l"(w) : "memory");
}
__device__ __forceinline__ float poll_tag(const unsigned long long* a, unsigned tag) {
    unsigned long long w;
    do { w = ld_tag(a); } while ((unsigned)(w >> 32) != tag);
    return __uint_as_float((unsigned)w);
}

// ---- packed f32x2 helpers ----
__device__ __forceinline__ unsigned long long f32x2_pack(float lo, float hi) {
    unsigned long long v;
    asm("mov.b64 %0,{%1,%2};" : "=l"(v) : "f"(lo), "f"(hi));
    return v;
}
__device__ __forceinline__ float f32x2_sum(unsigned long long v) {
    float lo, hi;
    asm("mov.b64 {%0,%1},%2;" : "=f"(lo), "=f"(hi) : "l"(v));
    return lo + hi;
}
__device__ __forceinline__ unsigned long long fma2(unsigned long long a,
                                                   unsigned long long b,
                                                   unsigned long long c) {
    unsigned long long d;
    asm("fma.rn.f32x2 %0,%1,%2,%3;" : "=l"(d) : "l"(a), "l"(b), "l"(c));
    return d;
}

// =====================================================================
// Kernel 1: prep — tag clear + init, xw1 GEMM, VOutB GEMM
// blocks 0..255: xw1 tiles; 256..511: VOutB tiles; 512..519: tags/init
// =====================================================================
__global__ void __launch_bounds__(256) prep_kernel(
    const int* __restrict__ Y, const float* __restrict__ h0,
    const float* __restrict__ emb, const float* __restrict__ W_ih1,
    const float* __restrict__ b_ih1, const float* __restrict__ b_hh1,
    const float* __restrict__ att_V, const float* __restrict__ att_b,
    const float* __restrict__ outEnc)
{
    int bid = blockIdx.x, tid = threadIdx.x;
    if (bid >= 512) {
        int base = (bid - 512) * 256 + tid;
        for (int i = base; i < 3 * NSTEP * H; i += 8 * 256) {
            int l = i / (NSTEP * H);
            int rem = i - l * (NSTEP * H);
            int t = rem / H + 1;
            int u = rem % H;
            g_Ht64[l * LSTRIDE + t * H + u] = 0xFFFFFFFF00000000ULL;
        }
        if (bid == 519) {  // t=0 slots, tag 0 (disjoint from clears)
            store_tag(&g_Ht64[0 * LSTRIDE + tid], h0[0 * H + tid], 0u);
            store_tag(&g_Ht64[1 * LSTRIDE + tid], h0[1 * H + tid], 0u);
            store_tag(&g_Ht64[2 * LSTRIDE + tid], h0[2 * H + tid], 0u);
        }
        return;
    }
    __shared__ float As[32][33];
    __shared__ float Bs[32][33];
    int mode = bid >> 8;       // 0 -> xw1, 1 -> VOutB
    int tb = bid & 255;
    int m0 = (tb & 7) * 32;
    int n0 = (tb >> 3) * 32;
    const float* Bsrc = mode ? outEnc : W_ih1;

    int tm = tid & 31;
    int tn = tid >> 5;
    int ar = tid >> 3, ak = (tid & 7) << 2;

    float acc0 = 0.f, acc1 = 0.f, acc2 = 0.f, acc3 = 0.f;
    for (int k0 = 0; k0 < H; k0 += 32) {
        const float* arow = mode ? (att_V + (m0 + ar) * H) : (emb + Y[m0 + ar] * H);
        float4 a4 = *(const float4*)(arow + k0 + ak);
        As[ar][ak] = a4.x; As[ar][ak + 1] = a4.y; As[ar][ak + 2] = a4.z; As[ar][ak + 3] = a4.w;
        float4 b4 = *(const float4*)(Bsrc + (n0 + ar) * H + k0 + ak);
        Bs[ar][ak] = b4.x; Bs[ar][ak + 1] = b4.y; Bs[ar][ak + 2] = b4.z; Bs[ar][ak + 3] = b4.w;
        __syncthreads();
#pragma unroll
        for (int kk = 0; kk < 32; kk++) {
            float a = As[tm][kk];
            acc0 += a * Bs[tn * 4 + 0][kk];
            acc1 += a * Bs[tn * 4 + 1][kk];
            acc2 += a * Bs[tn * 4 + 2][kk];
            acc3 += a * Bs[tn * 4 + 3][kk];
        }
        __syncthreads();
    }
    int m = m0 + tm;
    float* Cd = mode ? g_VOutB : g_xw1;
    float accs[4] = {acc0, acc1, acc2, acc3};
#pragma unroll
    for (int jj = 0; jj < 4; jj++) {
        int n = n0 + tn * 4 + jj;
        float b = mode ? att_b[m] : (b_ih1[n] + b_hh1[n]);
        Cd[m * 1024 + n] = accs[jj] + b;
    }
}

// =====================================================================
// Kernel 2 (fused): blocks 0..95 = persistent LSTM recurrence,
//                   blocks 96..223 = attention+MLP (2 steps each)
// =====================================================================
__global__ void __launch_bounds__(256) fused_kernel(
    const float* __restrict__ h0, const float* __restrict__ c0,
    const float* __restrict__ Wih2, const float* __restrict__ Whh2,
    const float* __restrict__ bih2, const float* __restrict__ bhh2,
    const float* __restrict__ Wih3, const float* __restrict__ Whh3,
    const float* __restrict__ bih3, const float* __restrict__ bhh3,
    const float* __restrict__ Whh1,
    const float* __restrict__ outEnc, const float* __restrict__ attW,
    const float* __restrict__ attVec,
    const float* __restrict__ w1, const float* __restrict__ b1,
    const float* __restrict__ w2, const float* __restrict__ b2,
    const float* __restrict__ w3, const float* __restrict__ b3,
    float* __restrict__ outp)
{
    // ---- rnn shared: double-buffered input vector [x(256) | h_own(256)] ----
    __shared__ float sIn[2][2 * H];
    // ---- attn shared ----
    __shared__ float h2s[2][H];
    __shared__ float wss[2][H];
    __shared__ float avs[H];
    __shared__ float alp[2][SENC];
    __shared__ float red[40];
    __shared__ float vbuf[2][2 * H];
    __shared__ float v1s[2][H];
    __shared__ float v2s[2][H];

    int tid = threadIdx.x, lane = tid & 31, warp = tid >> 5;

    if (blockIdx.x < RNN_BLOCKS) {
        // ============================ RNN ============================
        int l = blockIdx.x >> 5;
        int p = blockIdx.x & 31;
        int u = p * UPC + warp;            // unit owned by this warp

        const float* Wih = (l == 1) ? Wih2 : ((l == 2) ? Wih3 : (const float*)0);
        const float* Whh = (l == 0) ? Whh1 : ((l == 1) ? Whh2 : Whh3);
        const float* bih = (l == 1) ? bih2 : bih3;
        const float* bhh = (l == 1) ? bhh2 : bhh3;

        // weights -> packed f32x2 registers. Row = [Wih(256) | Whh(256)] cols.
        unsigned long long Wp[4][8];
#pragma unroll
        for (int r = 0; r < 4; r++) {
            int grow = r * H + u;
#pragma unroll
            for (int m = 0; m < 4; m++) {
                float4 w;
                if (m < 2) {
                    if (l == 0) w = make_float4(0.f, 0.f, 0.f, 0.f);
                    else        w = *(const float4*)(Wih + grow * H + 4 * (lane + 32 * m));
                } else {
                    w = *(const float4*)(Whh + grow * H + 4 * (lane + 32 * (m - 2)));
                }
                Wp[r][2 * m]     = f32x2_pack(w.x, w.y);
                Wp[r][2 * m + 1] = f32x2_pack(w.z, w.w);
            }
        }
        // per-lane gate bias (lanes 0..3 meaningful), layers 1/2 only
        float biasreg = 0.f;
        if (l > 0) biasreg = bih[(lane & 3) * H + u] + bhh[(lane & 3) * H + u];

        float creg = 0.f, hreg = 0.f;
        if (lane == 0) {
            creg = c0[l * H + u];
            hreg = h0[l * H + u];
        }
        if (l == 0) { sIn[0][tid] = 0.f; sIn[1][tid] = 0.f; }   // x-halves unused
        __syncthreads();

        unsigned long long* ownB = g_Ht64 + l * LSTRIDE;
        unsigned long long* depB = g_Ht64 + (l - 1) * LSTRIDE;
        bool ownSlot = (tid >= p * UPC) && (tid < p * UPC + UPC);

        for (unsigned t = 1; t <= NSTEP; t++) {
            float* buf = sIn[t & 1];
            // layer-0 per-step bias prefetch (independent of polls)
            float bstep = 0.f;
            if (l == 0 && lane < 4)
                bstep = __ldcg(&g_xw1[(t - 1) * 1024 + lane * H + u]);
            // own unit from register
            if (lane == 0) buf[H + u] = hreg;
            // dual concurrent polls: own-layer h(t-1) + lower-layer h(t)
            {
                bool dA = ownSlot;
                bool dB = (l == 0);
                const unsigned long long* pA = ownB + (t - 1) * H + tid;
                const unsigned long long* pB = depB + t * H + tid;
                unsigned tagA = t - 1, tagB = t;
                while (!(dA && dB)) {
                    unsigned long long xA = 0, xB = 0;
                    if (!dA) xA = ld_tag(pA);
                    if (!dB) xB = ld_tag(pB);
                    if (!dA && (unsigned)(xA >> 32) == tagA) {
                        buf[H + tid] = __uint_as_float((unsigned)xA); dA = true;
                    }
                    if (!dB && (unsigned)(xB >> 32) == tagB) {
                        buf[tid] = __uint_as_float((unsigned)xB); dB = true;
                    }
                }
            }
            __syncthreads();

            // matvec: 4 gates, packed f32x2 FMA
            unsigned long long acc0 = 0ULL, acc1 = 0ULL, acc2 = 0ULL, acc3 = 0ULL;
#pragma unroll
            for (int m = 0; m < 4; m++) {
                float4 x = *(const float4*)(buf + 4 * (lane + 32 * m));
                unsigned long long xlo = f32x2_pack(x.x, x.y);
                unsigned long long xhi = f32x2_pack(x.z, x.w);
                acc0 = fma2(Wp[0][2 * m], xlo, acc0); acc0 = fma2(Wp[0][2 * m + 1], xhi, acc0);
                acc1 = fma2(Wp[1][2 * m], xlo, acc1); acc1 = fma2(Wp[1][2 * m + 1], xhi, acc1);
                acc2 = fma2(Wp[2][2 * m], xlo, acc2); acc2 = fma2(Wp[2][2 * m + 1], xhi, acc2);
                acc3 = fma2(Wp[3][2 * m], xlo, acc3); acc3 = fma2(Wp[3][2 * m + 1], xhi, acc3);
            }
            float s0 = f32x2_sum(acc0), s1 = f32x2_sum(acc1);
            float s2 = f32x2_sum(acc2), s3 = f32x2_sum(acc3);
#pragma unroll
            for (int off = 16; off > 0; off >>= 1) {
                s0 += __shfl_xor_sync(0xffffffffu, s0, off);
                s1 += __shfl_xor_sync(0xffffffffu, s1, off);
                s2 += __shfl_xor_sync(0xffffffffu, s2, off);
                s3 += __shfl_xor_sync(0xffffffffu, s3, off);
            }
            // lanes 0..3 compute activations of gates i,f,g,o in parallel
            float sv = (lane == 1) ? s1 : (lane == 2) ? s2 : (lane == 3) ? s3 : s0;
            float raw = sv + ((l == 0) ? bstep : biasreg);
            float kk = (lane == 2) ? 2.0f : 1.0f;
            float e = __expf(-kk * raw);
            float sg = __fdividef(1.0f, 1.0f + e);
            float act = (lane == 2) ? fmaf(2.0f, sg, -1.0f) : sg;   // tanh = 2*sig(2x)-1
            float fg = __shfl_sync(0xffffffffu, act, 1);
            float gg = __shfl_sync(0xffffffffu, act, 2);
            float og = __shfl_sync(0xffffffffu, act, 3);
            if (lane == 0) {
                float c = fmaf(fg, creg, act * gg);                 // act = sig(i)
                float e2 = __expf(-2.0f * c);
                float th = fmaf(2.0f, __fdividef(1.0f, 1.0f + e2), -1.0f);
                float h = og * th;
                creg = c; hreg = h;
                store_tag(ownB + t * H + u, h, t);
            }
            // single barrier/step: sIn double-buffered by t parity.
        }
        return;
    }

    // ============================ ATTENTION + MLP ============================
    int t0 = (blockIdx.x - RNN_BLOCKS) * 2;

    avs[tid] = attVec[tid];
    h2s[0][tid] = poll_tag(&g_Ht64[2 * LSTRIDE + (t0 + 1) * H + tid], (unsigned)(t0 + 1));
    h2s[1][tid] = poll_tag(&g_Ht64[2 * LSTRIDE + (t0 + 2) * H + tid], (unsigned)(t0 + 2));
    __syncthreads();

    // WS[s][h] = att_W[h,:] . h2[s]
    {
        float s0 = 0.f, s1 = 0.f;
        const float4* wr = (const float4*)(attW + tid * H);
        const float4* x0 = (const float4*)h2s[0];
        const float4* x1 = (const float4*)h2s[1];
#pragma unroll 8
        for (int k = 0; k < 64; k++) {
            float4 w = wr[k], a = x0[k], b = x1[k];
            s0 += w.x * a.x + w.y * a.y + w.z * a.z + w.w * a.w;
            s1 += w.x * b.x + w.y * b.y + w.z * b.z + w.w * b.w;
        }
        wss[0][tid] = s0; wss[1][tid] = s1;
    }
    __syncthreads();

    // e[s] = sum_h av[h] * tanh(WS[h] + VOutB[h][s]) for both steps
    float e00 = 0.f, e01 = 0.f, e02 = 0.f, e03 = 0.f;
    float e10 = 0.f, e11 = 0.f, e12 = 0.f, e13 = 0.f;
    const float4* vb = (const float4*)g_VOutB;
#pragma unroll 4
    for (int h = 0; h < H; h++) {
        float a = avs[h], w0v = wss[0][h], w1v = wss[1][h];
        float4 v4 = vb[h * (SENC / 4) + tid];
        e00 = fmaf(a, tanh_poly(w0v + v4.x), e00);
        e01 = fmaf(a, tanh_poly(w0v + v4.y), e01);
        e02 = fmaf(a, tanh_poly(w0v + v4.z), e02);
        e03 = fmaf(a, tanh_poly(w0v + v4.w), e03);
        e10 = fmaf(a, tanh_poly(w1v + v4.x), e10);
        e11 = fmaf(a, tanh_poly(w1v + v4.y), e11);
        e12 = fmaf(a, tanh_poly(w1v + v4.z), e12);
        e13 = fmaf(a, tanh_poly(w1v + v4.w), e13);
    }

    // softmax over 1024, both steps
    float mx0 = fmaxf(fmaxf(e00, e01), fmaxf(e02, e03));
    float mx1 = fmaxf(fmaxf(e10, e11), fmaxf(e12, e13));
#pragma unroll
    for (int off = 16; off > 0; off >>= 1) {
        mx0 = fmaxf(mx0, __shfl_xor_sync(0xffffffffu, mx0, off));
        mx1 = fmaxf(mx1, __shfl_xor_sync(0xffffffffu, mx1, off));
    }
    if (lane == 0) { red[warp] = mx0; red[8 + warp] = mx1; }
    __syncthreads();
    if (tid == 0) {
        float m0 = red[0], m1 = red[8];
#pragma unroll
        for (int i = 1; i < 8; i++) { m0 = fmaxf(m0, red[i]); m1 = fmaxf(m1, red[8 + i]); }
        red[32] = m0; red[33] = m1;
    }
    __syncthreads();
    mx0 = red[32]; mx1 = red[33];
    float x00 = __expf(e00 - mx0), x01 = __expf(e01 - mx0);
    float x02 = __expf(e02 - mx0), x03 = __expf(e03 - mx0);
    float x10 = __expf(e10 - mx1), x11 = __expf(e11 - mx1);
    float x12 = __expf(e12 - mx1), x13 = __expf(e13 - mx1);
    float sm0 = x00 + x01 + x02 + x03;
    float sm1 = x10 + x11 + x12 + x13;
#pragma unroll
    for (int off = 16; off > 0; off >>= 1) {
        sm0 += __shfl_xor_sync(0xffffffffu, sm0, off);
        sm1 += __shfl_xor_sync(0xffffffffu, sm1, off);
    }
    if (lane == 0) { red[16 + warp] = sm0; red[24 + warp] = sm1; }
    __syncthreads();
    if (tid == 0) {
        float s0 = 0.f, s1 = 0.f;
#pragma unroll
        for (int i = 0; i < 8; i++) { s0 += red[16 + i]; s1 += red[24 + i]; }
        red[34] = 1.0f / s0;
        red[35] = 1.0f / s1;
    }
    __syncthreads();
    float inv0 = red[34], inv1 = red[35];
    alp[0][4 * tid + 0] = x00 * inv0; alp[0][4 * tid + 1] = x01 * inv0;
    alp[0][4 * tid + 2] = x02 * inv0; alp[0][4 * tid + 3] = x03 * inv0;
    alp[1][4 * tid + 0] = x10 * inv1; alp[1][4 * tid + 1] = x11 * inv1;
    alp[1][4 * tid + 2] = x12 * inv1; alp[1][4 * tid + 3] = x13 * inv1;
    __syncthreads();

    // context[tid] = sum_s alpha[s] * outEnc[s][tid]
    float c0v = 0.f, c1v = 0.f;
#pragma unroll 4
    for (int s = 0; s < SENC; s++) {
        float v = __ldg(&outEnc[s * H + tid]);
        c0v = fmaf(alp[0][s], v, c0v);
        c1v = fmaf(alp[1][s], v, c1v);
    }
    vbuf[0][tid] = h2s[0][tid]; vbuf[0][H + tid] = c0v;
    vbuf[1][tid] = h2s[1][tid]; vbuf[1][H + tid] = c1v;
    __syncthreads();

    // v1 = relu(v @ w1^T + b1)
    {
        float s0 = b1[tid], s1 = s0;
        const float4* r = (const float4*)(w1 + tid * (2 * H));
        const float4* xa = (const float4*)vbuf[0];
        const float4* xb = (const float4*)vbuf[1];
#pragma unroll 8
        for (int k = 0; k < 128; k++) {
            float4 w = r[k], a = xa[k], b = xb[k];
            s0 += w.x * a.x + w.y * a.y + w.z * a.z + w.w * a.w;
            s1 += w.x * b.x + w.y * b.y + w.z * b.z + w.w * b.w;
        }
        v1s[0][tid] = fmaxf(s0, 0.f);
        v1s[1][tid] = fmaxf(s1, 0.f);
    }
    __syncthreads();
    // v2 = relu(v1 @ w2^T + b2)
    {
        float s0 = b2[tid], s1 = s0;
        const float4* r = (const float4*)(w2 + tid * H);
        const float4* xa = (const float4*)v1s[0];
        const float4* xb = (const float4*)v1s[1];
#pragma unroll 8
        for (int k = 0; k < 64; k++) {
            float4 w = r[k], a = xa[k], b = xb[k];
            s0 += w.x * a.x + w.y * a.y + w.z * a.z + w.w * a.w;
            s1 += w.x * b.x + w.y * b.y + w.z * b.z + w.w * b.w;
        }
        v2s[0][tid] = fmaxf(s0, 0.f);
        v2s[1][tid] = fmaxf(s1, 0.f);
    }
    __syncthreads();
    // out = v2 @ w3^T + b3
    if (tid < VOCAB) {
        float s0 = b3[tid], s1 = s0;
        const float4* r = (const float4*)(w3 + tid * H);
        const float4* xa = (const float4*)v2s[0];
        const float4* xb = (const float4*)v2s[1];
#pragma unroll 8
        for (int k = 0; k < 64; k++) {
            float4 w = r[k], a = xa[k], b = xb[k];
            s0 += w.x * a.x + w.y * a.y + w.z * a.z + w.w * a.w;
            s1 += w.x * b.x + w.y * b.y + w.z * b.z + w.w * b.w;
        }
        outp[(t0 + 0) * VOCAB + tid] = s0;
        outp[(t0 + 1) * VOCAB + tid] = s1;
    }
}

extern "C" void kernel_launch(void* const* d_in, const int* in_sizes, int n_in,
                              void* d_out, int out_size) {
    const int*   Y      = (const int*)d_in[0];
    const float* h0     = (const float*)d_in[1];
    const float* c0     = (const float*)d_in[2];
    const float* outEnc = (const float*)d_in[3];
    const float* emb    = (const float*)d_in[4];
    const float* W_ih1  = (const float*)d_in[5];
    const float* W_hh1  = (const float*)d_in[6];
    const float* b_ih1  = (const float*)d_in[7];
    const float* b_hh1  = (const float*)d_in[8];
    const float* W_ih2  = (const float*)d_in[9];
    const float* W_hh2  = (const float*)d_in[10];
    const float* b_ih2  = (const float*)d_in[11];
    const float* b_hh2  = (const float*)d_in[12];
    const float* W_ih3  = (const float*)d_in[13];
    const float* W_hh3  = (const float*)d_in[14];
    const float* b_ih3  = (const float*)d_in[15];
    const float* b_hh3  = (const float*)d_in[16];
    const float* attVec = (const float*)d_in[17];
    const float* attW   = (const float*)d_in[18];
    const float* attV   = (const float*)d_in[19];
    const float* attB   = (const float*)d_in[20];
    const float* w1     = (const float*)d_in[21];
    const float* b1     = (const float*)d_in[22];
    const float* w2     = (const float*)d_in[23];
    const float* b2     = (const float*)d_in[24];
    const float* w3     = (const float*)d_in[25];
    const float* b3     = (const float*)d_in[26];
    float* outp = (float*)d_out;

    prep_kernel<<<520, 256>>>(Y, h0, emb, W_ih1, b_ih1, b_hh1, attV, attB, outEnc);
    fused_kernel<<<RNN_BLOCKS + ATTN_BLOCKS, 256>>>(
        h0, c0, W_ih2, W_hh2, b_ih2, b_hh2, W_ih3, W_hh3, b_ih3, b_hh3, W_hh1,
        outEnc, attW, attVec, w1, b1, w2, b2, w3, b3, outp);
}

// round 7
// speedup vs baseline: 1.5952x; 1.0442x over previous
#include <cuda_runtime.h>
#include <cuda_bf16.h>
#include <math.h>
#include <cstdio>

#define H 256
#define SENC 1024
#define NSTEP 256
#define VOCAB 47
#define UPC 8
#define LSTRIDE ((NSTEP + 1) * H)
#define RNN_BLOCKS 96
#define ATTN_BLOCKS 128

// ---------------- device scratch ----------------
__device__ float g_xw1[NSTEP * 1024];              // emb[Y[t]]@W_ih1^T + b_ih1 + b_hh1
__device__ float g_VOutB[H * SENC];                // att_V@outEnc^T + att_b
__device__ unsigned long long g_Ht64[3 * LSTRIDE]; // packed {tag<<32 | float bits}

// accurate-enough tanh for attention path (R2/R5-proven)
__device__ __forceinline__ float tanh_poly(float x) {
    float t = x * x;
    float p = fmaf(t, 0.0218694885f, -0.0539682540f);
    p = fmaf(t, p, 0.1333333333f);
    p = fmaf(t, p, -0.3333333333f);
    float y = fmaf(x * t, p, x);
    if (fabsf(x) > 0.5f) y = tanhf(x);
    return y;
}

// ---- aligned 8B scalar tag word: single-copy atomic on the plain .cg path ----
__device__ __forceinline__ unsigned long long ld_tag(const unsigned long long* a) {
    unsigned long long w;
    asm volatile("ld.global.cg.b64 %0,[%1];" : "=l"(w) : "l"(a) : "memory");
    return w;
}
__device__ __forceinline__ void store_tag(unsigned long long* a, float v, unsigned tag) {
    unsigned long long w = ((unsigned long long)tag << 32) |
                           (unsigned long long)__float_as_uint(v);
    asm volatile("st.global.cg.b64 [%0],%1;" :: "l"(a), "l"(w) : "memory");
}
// hot poll (rnn): tight loop
__device__ __forceinline__ float poll_tag(const unsigned long long* a, unsigned tag) {
    unsigned long long w;
    do { w = ld_tag(a); } while ((unsigned)(w >> 32) != tag);
    return __uint_as_float((unsigned)w);
}
// cold poll (attn): 1us backoff so we don't storm the producer's L2 lines
__device__ __forceinline__ float poll_tag_sleep(const unsigned long long* a, unsigned tag) {
    unsigned long long w = ld_tag(a);
    while ((unsigned)(w >> 32) != tag) { __nanosleep(1000); w = ld_tag(a); }
    return __uint_as_float((unsigned)w);
}

// ---- packed f32x2 helpers ----
__device__ __forceinline__ unsigned long long f32x2_pack(float lo, float hi) {
    unsigned long long v;
    asm("mov.b64 %0,{%1,%2};" : "=l"(v) : "f"(lo), "f"(hi));
    return v;
}
__device__ __forceinline__ float f32x2_sum(unsigned long long v) {
    float lo, hi;
    asm("mov.b64 {%0,%1},%2;" : "=f"(lo), "=f"(hi) : "l"(v));
    return lo + hi;
}
__device__ __forceinline__ unsigned long long fma2(unsigned long long a,
                                                   unsigned long long b,
                                                   unsigned long long c) {
    unsigned long long d;
    asm("fma.rn.f32x2 %0,%1,%2,%3;" : "=l"(d) : "l"(a), "l"(b), "l"(c));
    return d;
}

// =====================================================================
// Kernel 1: prep — tag clear + init, xw1 GEMM, VOutB GEMM
// blocks 0..255: xw1 tiles; 256..511: VOutB tiles; 512..519: tags/init
// =====================================================================
__global__ void __launch_bounds__(256) prep_kernel(
    const int* __restrict__ Y, const float* __restrict__ h0,
    const float* __restrict__ emb, const float* __restrict__ W_ih1,
    const float* __restrict__ b_ih1, const float* __restrict__ b_hh1,
    const float* __restrict__ att_V, const float* __restrict__ att_b,
    const float* __restrict__ outEnc)
{
    int bid = blockIdx.x, tid = threadIdx.x;
    if (bid >= 512) {
        int base = (bid - 512) * 256 + tid;
        for (int i = base; i < 3 * NSTEP * H; i += 8 * 256) {
            int l = i / (NSTEP * H);
            int rem = i - l * (NSTEP * H);
            int t = rem / H + 1;
            int u = rem % H;
            g_Ht64[l * LSTRIDE + t * H + u] = 0xFFFFFFFF00000000ULL;
        }
        if (bid == 519) {  // t=0 slots, tag 0 (disjoint from clears)
            store_tag(&g_Ht64[0 * LSTRIDE + tid], h0[0 * H + tid], 0u);
            store_tag(&g_Ht64[1 * LSTRIDE + tid], h0[1 * H + tid], 0u);
            store_tag(&g_Ht64[2 * LSTRIDE + tid], h0[2 * H + tid], 0u);
        }
        return;
    }
    __shared__ float As[32][33];
    __shared__ float Bs[32][33];
    int mode = bid >> 8;       // 0 -> xw1, 1 -> VOutB
    int tb = bid & 255;
    int m0 = (tb & 7) * 32;
    int n0 = (tb >> 3) * 32;
    const float* Bsrc = mode ? outEnc : W_ih1;

    int tm = tid & 31;
    int tn = tid >> 5;
    int ar = tid >> 3, ak = (tid & 7) << 2;

    float acc0 = 0.f, acc1 = 0.f, acc2 = 0.f, acc3 = 0.f;
    for (int k0 = 0; k0 < H; k0 += 32) {
        const float* arow = mode ? (att_V + (m0 + ar) * H) : (emb + Y[m0 + ar] * H);
        float4 a4 = *(const float4*)(arow + k0 + ak);
        As[ar][ak] = a4.x; As[ar][ak + 1] = a4.y; As[ar][ak + 2] = a4.z; As[ar][ak + 3] = a4.w;
        float4 b4 = *(const float4*)(Bsrc + (n0 + ar) * H + k0 + ak);
        Bs[ar][ak] = b4.x; Bs[ar][ak + 1] = b4.y; Bs[ar][ak + 2] = b4.z; Bs[ar][ak + 3] = b4.w;
        __syncthreads();
#pragma unroll
        for (int kk = 0; kk < 32; kk++) {
            float a = As[tm][kk];
            acc0 += a * Bs[tn * 4 + 0][kk];
            acc1 += a * Bs[tn * 4 + 1][kk];
            acc2 += a * Bs[tn * 4 + 2][kk];
            acc3 += a * Bs[tn * 4 + 3][kk];
        }
        __syncthreads();
    }
    int m = m0 + tm;
    float* Cd = mode ? g_VOutB : g_xw1;
    float accs[4] = {acc0, acc1, acc2, acc3};
#pragma unroll
    for (int jj = 0; jj < 4; jj++) {
        int n = n0 + tn * 4 + jj;
        float b = mode ? att_b[m] : (b_ih1[n] + b_hh1[n]);
        Cd[m * 1024 + n] = accs[jj] + b;
    }
}

// =====================================================================
// Kernel 2 (fused): blocks 0..95 = persistent LSTM recurrence,
//                   blocks 96..223 = attention+MLP (2 steps each)
// =====================================================================
__global__ void __launch_bounds__(256) fused_kernel(
    const float* __restrict__ h0, const float* __restrict__ c0,
    const float* __restrict__ Wih2, const float* __restrict__ Whh2,
    const float* __restrict__ bih2, const float* __restrict__ bhh2,
    const float* __restrict__ Wih3, const float* __restrict__ Whh3,
    const float* __restrict__ bih3, const float* __restrict__ bhh3,
    const float* __restrict__ Whh1,
    const float* __restrict__ outEnc, const float* __restrict__ attW,
    const float* __restrict__ attVec,
    const float* __restrict__ w1, const float* __restrict__ b1,
    const float* __restrict__ w2, const float* __restrict__ b2,
    const float* __restrict__ w3, const float* __restrict__ b3,
    float* __restrict__ outp)
{
    // ---- rnn shared: double-buffered input vector [x(256) | h_own(256)] ----
    __shared__ float sIn[2][2 * H];
    // ---- attn shared ----
    __shared__ float h2s[2][H];
    __shared__ float wss[2][H];
    __shared__ float avs[H];
    __shared__ float alp[2][SENC];
    __shared__ float red[40];
    __shared__ float vbuf[2][2 * H];
    __shared__ float v1s[2][H];
    __shared__ float v2s[2][H];

    int tid = threadIdx.x, lane = tid & 31, warp = tid >> 5;

    if (blockIdx.x < RNN_BLOCKS) {
        // ============================ RNN ============================
        int l = blockIdx.x >> 5;
        int p = blockIdx.x & 31;
        int u = p * UPC + warp;            // unit owned by this warp

        const float* Wih = (l == 1) ? Wih2 : ((l == 2) ? Wih3 : (const float*)0);
        const float* Whh = (l == 0) ? Whh1 : ((l == 1) ? Whh2 : Whh3);
        const float* bih = (l == 1) ? bih2 : bih3;
        const float* bhh = (l == 1) ? bhh2 : bhh3;

        // weights -> packed f32x2 registers. Row = [Wih(256) | Whh(256)] cols.
        unsigned long long Wp[4][8];
#pragma unroll
        for (int r = 0; r < 4; r++) {
            int grow = r * H + u;
#pragma unroll
            for (int m = 0; m < 4; m++) {
                float4 w;
                if (m < 2) {
                    if (l == 0) w = make_float4(0.f, 0.f, 0.f, 0.f);
                    else        w = *(const float4*)(Wih + grow * H + 4 * (lane + 32 * m));
                } else {
                    w = *(const float4*)(Whh + grow * H + 4 * (lane + 32 * (m - 2)));
                }
                Wp[r][2 * m]     = f32x2_pack(w.x, w.y);
                Wp[r][2 * m + 1] = f32x2_pack(w.z, w.w);
            }
        }
        // per-lane gate bias (lanes 0..3 meaningful), layers 1/2 only
        float biasreg = 0.f;
        if (l > 0) biasreg = bih[(lane & 3) * H + u] + bhh[(lane & 3) * H + u];

        float creg = 0.f, hreg = 0.f;
        if (lane == 0) {
            creg = c0[l * H + u];
            hreg = h0[l * H + u];
        }
        if (l == 0) { sIn[0][tid] = 0.f; sIn[1][tid] = 0.f; }   // x-halves unused
        __syncthreads();

        unsigned long long* ownB = g_Ht64 + l * LSTRIDE;
        unsigned long long* depB = g_Ht64 + (l - 1) * LSTRIDE;
        bool ownSlot = (tid >= p * UPC) && (tid < p * UPC + UPC);

        long long tstart = (tid == 0) ? clock64() : 0;

        for (unsigned t = 1; t <= NSTEP; t++) {
            float* buf = sIn[t & 1];
            // layer-0 per-step bias prefetch (independent of polls)
            float bstep = 0.f;
            if (l == 0 && lane < 4)
                bstep = __ldcg(&g_xw1[(t - 1) * 1024 + lane * H + u]);
            // own unit from register
            if (lane == 0) buf[H + u] = hreg;
            // dual concurrent polls: own-layer h(t-1) + lower-layer h(t)
            {
                bool dA = ownSlot;
                bool dB = (l == 0);
                const unsigned long long* pA = ownB + (t - 1) * H + tid;
                const unsigned long long* pB = depB + t * H + tid;
                unsigned tagA = t - 1, tagB = t;
                while (!(dA && dB)) {
                    unsigned long long xA = 0, xB = 0;
                    if (!dA) xA = ld_tag(pA);
                    if (!dB) xB = ld_tag(pB);
                    if (!dA && (unsigned)(xA >> 32) == tagA) {
                        buf[H + tid] = __uint_as_float((unsigned)xA); dA = true;
                    }
                    if (!dB && (unsigned)(xB >> 32) == tagB) {
                        buf[tid] = __uint_as_float((unsigned)xB); dB = true;
                    }
                }
            }
            __syncthreads();

            // matvec: 4 gates, packed f32x2 FMA
            unsigned long long acc0 = 0ULL, acc1 = 0ULL, acc2 = 0ULL, acc3 = 0ULL;
#pragma unroll
            for (int m = 0; m < 4; m++) {
                float4 x = *(const float4*)(buf + 4 * (lane + 32 * m));
                unsigned long long xlo = f32x2_pack(x.x, x.y);
                unsigned long long xhi = f32x2_pack(x.z, x.w);
                acc0 = fma2(Wp[0][2 * m], xlo, acc0); acc0 = fma2(Wp[0][2 * m + 1], xhi, acc0);
                acc1 = fma2(Wp[1][2 * m], xlo, acc1); acc1 = fma2(Wp[1][2 * m + 1], xhi, acc1);
                acc2 = fma2(Wp[2][2 * m], xlo, acc2); acc2 = fma2(Wp[2][2 * m + 1], xhi, acc2);
                acc3 = fma2(Wp[3][2 * m], xlo, acc3); acc3 = fma2(Wp[3][2 * m + 1], xhi, acc3);
            }
            float s0 = f32x2_sum(acc0), s1 = f32x2_sum(acc1);
            float s2 = f32x2_sum(acc2), s3 = f32x2_sum(acc3);
#pragma unroll
            for (int off = 16; off > 0; off >>= 1) {
                s0 += __shfl_xor_sync(0xffffffffu, s0, off);
                s1 += __shfl_xor_sync(0xffffffffu, s1, off);
                s2 += __shfl_xor_sync(0xffffffffu, s2, off);
                s3 += __shfl_xor_sync(0xffffffffu, s3, off);
            }
            // lanes 0..3 compute activations of gates i,f,g,o in parallel
            float sv = (lane == 1) ? s1 : (lane == 2) ? s2 : (lane == 3) ? s3 : s0;
            float raw = sv + ((l == 0) ? bstep : biasreg);
            float kk = (lane == 2) ? 2.0f : 1.0f;
            float e = __expf(-kk * raw);
            float sg = __fdividef(1.0f, 1.0f + e);
            float act = (lane == 2) ? fmaf(2.0f, sg, -1.0f) : sg;   // tanh = 2*sig(2x)-1
            float fg = __shfl_sync(0xffffffffu, act, 1);
            float gg = __shfl_sync(0xffffffffu, act, 2);
            float og = __shfl_sync(0xffffffffu, act, 3);
            if (lane == 0) {
                float c = fmaf(fg, creg, act * gg);                 // act = sig(i)
                float e2 = __expf(-2.0f * c);
                float th = fmaf(2.0f, __fdividef(1.0f, 1.0f + e2), -1.0f);
                float h = og * th;
                creg = c; hreg = h;
                store_tag(ownB + t * H + u, h, t);
            }
            // single barrier/step: sIn double-buffered by t parity.
        }
        if (tid == 0 && p == 0) {
            long long dt = clock64() - tstart;
            printf("DIAG rnn L%d: %lld cyc total, %lld cyc/step\n", l, dt, dt / NSTEP);
        }
        return;
    }

    // ============================ ATTENTION + MLP ============================
    int t0 = (blockIdx.x - RNN_BLOCKS) * 2;

    avs[tid] = attVec[tid];
    h2s[0][tid] = poll_tag_sleep(&g_Ht64[2 * LSTRIDE + (t0 + 1) * H + tid], (unsigned)(t0 + 1));
    h2s[1][tid] = poll_tag_sleep(&g_Ht64[2 * LSTRIDE + (t0 + 2) * H + tid], (unsigned)(t0 + 2));
    __syncthreads();
    if (tid == 0 && blockIdx.x == RNN_BLOCKS + ATTN_BLOCKS - 1)
        printf("DIAG attn last block got h2 at clk %lld\n", clock64());

    // WS[s][h] = att_W[h,:] . h2[s]
    {
        float s0 = 0.f, s1 = 0.f;
        const float4* wr = (const float4*)(attW + tid * H);
        const float4* x0 = (const float4*)h2s[0];
        const float4* x1 = (const float4*)h2s[1];
#pragma unroll 8
        for (int k = 0; k < 64; k++) {
            float4 w = wr[k], a = x0[k], b = x1[k];
            s0 += w.x * a.x + w.y * a.y + w.z * a.z + w.w * a.w;
            s1 += w.x * b.x + w.y * b.y + w.z * b.z + w.w * b.w;
        }
        wss[0][tid] = s0; wss[1][tid] = s1;
    }
    __syncthreads();

    // e[s] = sum_h av[h] * tanh(WS[h] + VOutB[h][s]) for both steps
    float e00 = 0.f, e01 = 0.f, e02 = 0.f, e03 = 0.f;
    float e10 = 0.f, e11 = 0.f, e12 = 0.f, e13 = 0.f;
    const float4* vb = (const float4*)g_VOutB;
#pragma unroll 4
    for (int h = 0; h < H; h++) {
        float a = avs[h], w0v = wss[0][h], w1v = wss[1][h];
        float4 v4 = vb[h * (SENC / 4) + tid];
        e00 = fmaf(a, tanh_poly(w0v + v4.x), e00);
        e01 = fmaf(a, tanh_poly(w0v + v4.y), e01);
        e02 = fmaf(a, tanh_poly(w0v + v4.z), e02);
        e03 = fmaf(a, tanh_poly(w0v + v4.w), e03);
        e10 = fmaf(a, tanh_poly(w1v + v4.x), e10);
        e11 = fmaf(a, tanh_poly(w1v + v4.y), e11);
        e12 = fmaf(a, tanh_poly(w1v + v4.z), e12);
        e13 = fmaf(a, tanh_poly(w1v + v4.w), e13);
    }

    // softmax over 1024, both steps
    float mx0 = fmaxf(fmaxf(e00, e01), fmaxf(e02, e03));
    float mx1 = fmaxf(fmaxf(e10, e11), fmaxf(e12, e13));
#pragma unroll
    for (int off = 16; off > 0; off >>= 1) {
        mx0 = fmaxf(mx0, __shfl_xor_sync(0xffffffffu, mx0, off));
        mx1 = fmaxf(mx1, __shfl_xor_sync(0xffffffffu, mx1, off));
    }
    if (lane == 0) { red[warp] = mx0; red[8 + warp] = mx1; }
    __syncthreads();
    if (tid == 0) {
        float m0 = red[0], m1 = red[8];
#pragma unroll
        for (int i = 1; i < 8; i++) { m0 = fmaxf(m0, red[i]); m1 = fmaxf(m1, red[8 + i]); }
        red[32] = m0; red[33] = m1;
    }
    __syncthreads();
    mx0 = red[32]; mx1 = red[33];
    float x00 = __expf(e00 - mx0), x01 = __expf(e01 - mx0);
    float x02 = __expf(e02 - mx0), x03 = __expf(e03 - mx0);
    float x10 = __expf(e10 - mx1), x11 = __expf(e11 - mx1);
    float x12 = __expf(e12 - mx1), x13 = __expf(e13 - mx1);
    float sm0 = x00 + x01 + x02 + x03;
    float sm1 = x10 + x11 + x12 + x13;
#pragma unroll
    for (int off = 16; off > 0; off >>= 1) {
        sm0 += __shfl_xor_sync(0xffffffffu, sm0, off);
        sm1 += __shfl_xor_sync(0xffffffffu, sm1, off);
    }
    if (lane == 0) { red[16 + warp] = sm0; red[24 + warp] = sm1; }
    __syncthreads();
    if (tid == 0) {
        float s0 = 0.f, s1 = 0.f;
#pragma unroll
        for (int i = 0; i < 8; i++) { s0 += red[16 + i]; s1 += red[24 + i]; }
        red[34] = 1.0f / s0;
        red[35] = 1.0f / s1;
    }
    __syncthreads();
    float inv0 = red[34], inv1 = red[35];
    alp[0][4 * tid + 0] = x00 * inv0; alp[0][4 * tid + 1] = x01 * inv0;
    alp[0][4 * tid + 2] = x02 * inv0; alp[0][4 * tid + 3] = x03 * inv0;
    alp[1][4 * tid + 0] = x10 * inv1; alp[1][4 * tid + 1] = x11 * inv1;
    alp[1][4 * tid + 2] = x12 * inv1; alp[1][4 * tid + 3] = x13 * inv1;
    __syncthreads();

    // context[tid] = sum_s alpha[s] * outEnc[s][tid]
    float c0v = 0.f, c1v = 0.f;
#pragma unroll 4
    for (int s = 0; s < SENC; s++) {
        float v = __ldg(&outEnc[s * H + tid]);
        c0v = fmaf(alp[0][s], v, c0v);
        c1v = fmaf(alp[1][s], v, c1v);
    }
    vbuf[0][tid] = h2s[0][tid]; vbuf[0][H + tid] = c0v;
    vbuf[1][tid] = h2s[1][tid]; vbuf[1][H + tid] = c1v;
    __syncthreads();

    // v1 = relu(v @ w1^T + b1)
    {
        float s0 = b1[tid], s1 = s0;
        const float4* r = (const float4*)(w1 + tid * (2 * H));
        const float4* xa = (const float4*)vbuf[0];
        const float4* xb = (const float4*)vbuf[1];
#pragma unroll 8
        for (int k = 0; k < 128; k++) {
            float4 w = r[k], a = xa[k], b = xb[k];
            s0 += w.x * a.x + w.y * a.y + w.z * a.z + w.w * a.w;
            s1 += w.x * b.x + w.y * b.y + w.z * b.z + w.w * b.w;
        }
        v1s[0][tid] = fmaxf(s0, 0.f);
        v1s[1][tid] = fmaxf(s1, 0.f);
    }
    __syncthreads();
    // v2 = relu(v1 @ w2^T + b2)
    {
        float s0 = b2[tid], s1 = s0;
        const float4* r = (const float4*)(w2 + tid * H);
        const float4* xa = (const float4*)v1s[0];
        const float4* xb = (const float4*)v1s[1];
#pragma unroll 8
        for (int k = 0; k < 64; k++) {
            float4 w = r[k], a = xa[k], b = xb[k];
            s0 += w.x * a.x + w.y * a.y + w.z * a.z + w.w * a.w;
            s1 += w.x * b.x + w.y * b.y + w.z * b.z + w.w * b.w;
        }
        v2s[0][tid] = fmaxf(s0, 0.f);
        v2s[1][tid] = fmaxf(s1, 0.f);
    }
    __syncthreads();
    // out = v2 @ w3^T + b3
    if (tid < VOCAB) {
        float s0 = b3[tid], s1 = s0;
        const float4* r = (const float4*)(w3 + tid * H);
        const float4* xa = (const float4*)v2s[0];
        const float4* xb = (const float4*)v2s[1];
#pragma unroll 8
        for (int k = 0; k < 64; k++) {
            float4 w = r[k], a = xa[k], b = xb[k];
            s0 += w.x * a.x + w.y * a.y + w.z * a.z + w.w * a.w;
            s1 += w.x * b.x + w.y * b.y + w.z * b.z + w.w * b.w;
        }
        outp[(t0 + 0) * VOCAB + tid] = s0;
        outp[(t0 + 1) * VOCAB + tid] = s1;
    }
}

extern "C" void kernel_launch(void* const* d_in, const int* in_sizes, int n_in,
                              void* d_out, int out_size) {
    const int*   Y      = (const int*)d_in[0];
    const float* h0     = (const float*)d_in[1];
    const float* c0     = (const float*)d_in[2];
    const float* outEnc = (const float*)d_in[3];
    const float* emb    = (const float*)d_in[4];
    const float* W_ih1  = (const float*)d_in[5];
    const float* W_hh1  = (const float*)d_in[6];
    const float* b_ih1  = (const float*)d_in[7];
    const float* b_hh1  = (const float*)d_in[8];
    const float* W_ih2  = (const float*)d_in[9];
    const float* W_hh2  = (const float*)d_in[10];
    const float* b_ih2  = (const float*)d_in[11];
    const float* b_hh2  = (const float*)d_in[12];
    const float* W_ih3  = (const float*)d_in[13];
    const float* W_hh3  = (const float*)d_in[14];
    const float* b_ih3  = (const float*)d_in[15];
    const float* b_hh3  = (const float*)d_in[16];
    const float* attVec = (const float*)d_in[17];
    const float* attW   = (const float*)d_in[18];
    const float* attV   = (const float*)d_in[19];
    const float* attB   = (const float*)d_in[20];
    const float* w1     = (const float*)d_in[21];
    const float* b1     = (const float*)d_in[22];
    const float* w2     = (const float*)d_in[23];
    const float* b2     = (const float*)d_in[24];
    const float* w3     = (const float*)d_in[25];
    const float* b3     = (const float*)d_in[26];
    float* outp = (float*)d_out;

    prep_kernel<<<520, 256>>>(Y, h0, emb, W_ih1, b_ih1, b_hh1, attV, attB, outEnc);
    fused_kernel<<<RNN_BLOCKS + ATTN_BLOCKS, 256>>>(
        h0, c0, W_ih2, W_hh2, b_ih2, b_hh2, W_ih3, W_hh3, b_ih3, b_hh3, W_hh1,
        outEnc, attW, attVec, w1, b1, w2, b2, w3, b3, outp);
}